// round 5
// baseline (speedup 1.0000x reference)
#include <cuda_runtime.h>
#include <math.h>

#define MM 48
#define LL 48
#define NN 256
#define NPAIR 1176        // 48*49/2 (m<=k)
#define GT 128            // threads per sample group
#define ZPJ 10            // pairs per thread (128*10 >= 1176)
#define ROWF2 5           // suffix row = 10 floats = 5 float2

// Per-thread-blocked suffix scratch: [n][tg][l][5 float2]  ~62.9 MB.
// Written and read by the SAME thread within one kernel -> L2-resident.
__device__ float2 g_suf[(size_t)NN * GT * LL * ROWF2];

// Accurate f32 sincos: Cody-Waite FMA range reduction + Taylor polys.
// |x| < ~80, ~1-2 ulp, immune to --use_fast_math (no libm).
__device__ __forceinline__ void sincos_acc(float x, float* s, float* c) {
    float kf = rintf(x * 0.63661977236758134f);           // x * 2/pi
    int k = (int)kf;
    float r = fmaf(kf, -1.57079637050628662109375f, x);   // - k * fl32(pi/2)
    r = fmaf(kf, 4.37113882867379290e-8f, r);             // - k * lo correction
    float r2 = r * r;
    float ps = fmaf(r2, 2.7557314297e-06f, -1.9841270114e-04f);
    ps = fmaf(r2, ps, 8.3333337680e-03f);
    ps = fmaf(r2, ps, -1.6666667163e-01f);
    float sr = fmaf(r * r2, ps, r);
    float pc = fmaf(r2, -2.7557314297e-07f, 2.4760126951e-05f);
    pc = fmaf(r2, pc, -1.3888889225e-03f);
    pc = fmaf(r2, pc, 4.1666667908e-02f);
    float cr = fmaf(r2 * r2, pc, fmaf(r2, -0.5f, 1.0f));
    switch (k & 3) {
        case 0: *s = sr;  *c = cr;  break;
        case 1: *s = cr;  *c = -sr; break;
        case 2: *s = -sr; *c = -cr; break;
        default:*s = -cr; *c = sr;  break;
    }
}

// One fused kernel: per 128-thread group (2 groups/CTA, named barriers):
//   A) build the (a,b) tile in smem   B) backward suffix scan -> own rows
//   C) sequential zipper with register-resident per-pair prefix products.
__global__ __launch_bounds__(256) void fused_kernel(
    const float* __restrict__ inp,      // (N,L)
    const float* __restrict__ theta,    // (L,M)
    const float* __restrict__ coef,     // (M,)
    const float* __restrict__ rand_u,   // (L,N)
    float* __restrict__ out)            // N*L bits then N probs
{
    __shared__ float2 ab[2][LL * MM];           // per-group a/b tile (2 x 18.4KB)
    __shared__ float u_sh[2][LL];
    __shared__ float part[2][2][2][4];          // [gid][parity][s01][warp]

    const int tid  = threadIdx.x;
    const int gid  = tid >> 7;                  // sample group in CTA
    const int tg   = tid & 127;                 // thread-in-group
    const int lane = tg & 31, wg = tg >> 5;
    const int n    = blockIdx.x * 2 + gid;
    const int barid = gid + 1;                  // named barrier per group

    // ---- Phase A: embedding tile (f32 rounding matches reference) ----
    const float PI2F = 1.57079637050628662109375f;   // fl32(pi/2)
    float2* abg = ab[gid];
#pragma unroll
    for (int e = tg; e < LL * MM; e += GT) {
        int l = e / MM, m = e % MM;
        float ang = inp[n * LL + l] * ((float)(m + 1) * PI2F);
        float sa, ca; sincos_acc(ang, &sa, &ca);
        float st, ct; sincos_acc(theta[e], &st, &ct);
        float cf = coef[m];
        abg[e] = make_float2(cf * (ct * ca - st * sa),   // a (p=0)
                             cf * (st * ca + ct * sa));  // b (p=1)
    }
    if (tg < LL) u_sh[gid][tg] = rand_u[tg * NN + n];
    asm volatile("bar.sync %0, 128;" :: "r"(barid) : "memory");

    // ---- pair decode: thread owns 10 contiguous pairs of the m<=k triangle ----
    int pmk[ZPJ];        // m | k<<8
    float P[ZPJ];        // prefix products (pads exact 0)
    {
        int p0 = tg * ZPJ;
        int pc = (p0 < NPAIR) ? p0 : (NPAIR - 1);
        int m = 0, off = 0;
        while (off + (MM - m) <= pc) { off += MM - m; m++; }
        int k = m + (pc - off);
#pragma unroll
        for (int j = 0; j < ZPJ; j++) {
            pmk[j] = m | (k << 8);
            P[j] = (p0 + j < NPAIR) ? 1.0f : 0.0f;
            if (++k == MM) { ++m; k = m; }
            if (m >= MM) { m = MM - 1; k = MM - 1; }
        }
    }

    // ---- Phase B: backward suffix scan into this thread's own rows ----
    float2* myrow = g_suf + (size_t)(n * GT + tg) * (LL * ROWF2);
    {
        float run[ZPJ];
#pragma unroll
        for (int j = 0; j < ZPJ; j++) {
            int m = pmk[j] & 0xFF, k = (pmk[j] >> 8) & 0xFF;
            run[j] = (P[j] == 0.0f) ? 0.0f : ((m == k) ? 1.0f : 2.0f);
        }
        for (int l = LL - 1; l >= 0; l--) {
            float2* r = myrow + l * ROWF2;
#pragma unroll
            for (int q = 0; q < ROWF2; q++)
                r[q] = make_float2(run[2 * q], run[2 * q + 1]);
            const float2* abl = abg + l * MM;
#pragma unroll
            for (int j = 0; j < ZPJ; j++) {
                float2 vm = abl[pmk[j] & 0xFF];
                float2 vk = abl[(pmk[j] >> 8) & 0xFF];
                run[j] *= fmaf(vm.x, vk.x, vm.y * vk.y);
            }
        }
    }

    // ---- Phase C: zipper ----
    float2 sufA[ROWF2], sufB[ROWF2];
#pragma unroll
    for (int q = 0; q < ROWF2; q++) sufA[q] = myrow[q];   // row l=0 (just stored)

    float denom0 = 1.0f;
    int Kexp = 0;
    unsigned long long bits = 0ull;

    for (int l = 0; l < LL; l++) {
        float2* cu = (l & 1) ? sufB : sufA;
        float2* nx = (l & 1) ? sufA : sufB;
        if (l + 1 < LL) {                      // prefetch next row (L2, off chain)
#pragma unroll
            for (int q = 0; q < ROWF2; q++) nx[q] = myrow[(l + 1) * ROWF2 + q];
        }
        const float2* abl = abg + l * MM;
        float un = u_sh[gid][l];

        float aa[ZPJ], bb[ZPJ];
        float s0 = 0.0f, s1 = 0.0f;
#pragma unroll
        for (int j = 0; j < ZPJ; j++) {
            float sf = (j & 1) ? cu[j >> 1].y : cu[j >> 1].x;
            float2 vm = abl[pmk[j] & 0xFF];
            float2 vk = abl[(pmk[j] >> 8) & 0xFF];
            aa[j] = vm.x * vk.x;
            bb[j] = vm.y * vk.y;
            float ps = P[j] * sf;
            s0 = fmaf(ps, aa[j], s0);
            s1 = fmaf(ps, bb[j], s1);
        }
#pragma unroll
        for (int o = 16; o; o >>= 1) {
            s0 += __shfl_xor_sync(0xffffffffu, s0, o);
            s1 += __shfl_xor_sync(0xffffffffu, s1, o);
        }
        if (lane == 0) { part[gid][l & 1][0][wg] = s0; part[gid][l & 1][1][wg] = s1; }
        asm volatile("bar.sync %0, 128;" :: "r"(barid) : "memory");

        // redundant decision on all 128 threads (bitwise identical)
        const float* q0 = part[gid][l & 1][0];
        const float* q1 = part[gid][l & 1][1];
        float S0 = (q0[0] + q0[1]) + (q0[2] + q0[3]);
        float S1 = (q1[0] + q1[1]) + (q1[2] + q1[3]);
        float den = fabsf(S0 + S1);
        float p1  = fabsf(S1) / den;
        int bit = (un < p1) ? 1 : 0;
        if (l == 0) denom0 = den;
        int eb = (__float_as_int(den) >> 23) & 0xFF;     // exact 2^-k renorm
        int kk = eb ? (eb - 127) >> 1 : 0;
        Kexp += kk;
        float scale = __int_as_float((127 - kk) << 23);
        bits |= (unsigned long long)bit << l;
#pragma unroll
        for (int j = 0; j < ZPJ; j++)
            P[j] *= (bit ? bb[j] : aa[j]) * scale;       // lane-local update
    }

    // ---- epilogue: final inner + outputs ----
    float sf = 0.0f;
#pragma unroll
    for (int j = 0; j < ZPJ; j++) {
        int m = pmk[j] & 0xFF, k = (pmk[j] >> 8) & 0xFF;
        sf += ((m == k) ? 1.0f : 2.0f) * P[j];           // pads have P=0
    }
#pragma unroll
    for (int o = 16; o; o >>= 1) sf += __shfl_xor_sync(0xffffffffu, sf, o);
    if (lane == 0) part[gid][0][0][wg] = sf;
    asm volatile("bar.sync %0, 128;" :: "r"(barid) : "memory");

    if (tg < LL) out[n * LL + tg] = (float)((bits >> tg) & 1ull);
    if (tg == 0) {
        const float* q0 = part[gid][0][0];
        double Sf = (double)((q0[0] + q0[1]) + (q0[2] + q0[3]));  // inner_f * 2^-Kexp
        double pmv = ldexp(fabs(Sf), Kexp) / (double)denom0;
        out[NN * LL + n] = (float)pmv;
    }
}

extern "C" void kernel_launch(void* const* d_in, const int* in_sizes, int n_in,
                              void* d_out, int out_size) {
    const float* inp    = (const float*)d_in[0];   // (N,L)
    const float* theta  = (const float*)d_in[1];   // (L,M)
    const float* coef   = (const float*)d_in[2];   // (M,)
    const float* rand_u = (const float*)d_in[3];   // (L,N)
    float* out = (float*)d_out;

    fused_kernel<<<NN / 2, 256>>>(inp, theta, coef, rand_u, out);
}

// round 6
// speedup vs baseline: 2.8758x; 2.8758x over previous
#include <cuda_runtime.h>
#include <math.h>

#define MM 48
#define LL 48
#define NN 256
#define NT 128            // threads per CTA (= per sample)
#define ZPJ 12            // max pairs per thread (single-m segments)
#define CPW (NT * ZPJ)    // checkpoint row width = 1536 floats
#define CPROWS 12         // one checkpoint per 4 sites

// smem layout (floats): ab[4608] (float2*2304) | cp[12*1536] | u[48] | part[16]
#define SM_AB   0
#define SM_CP   (2 * LL * MM)
#define SM_U    (SM_CP + CPROWS * CPW)
#define SM_PART (SM_U + LL)
#define SMEMF   (SM_PART + 16)

// Accurate f32 sincos: Cody-Waite FMA range reduction + Taylor polys.
// |x| < ~80, ~1-2 ulp, immune to --use_fast_math (no libm).
__device__ __forceinline__ void sincos_acc(float x, float* s, float* c) {
    float kf = rintf(x * 0.63661977236758134f);           // x * 2/pi
    int k = (int)kf;
    float r = fmaf(kf, -1.57079637050628662109375f, x);   // - k * fl32(pi/2)
    r = fmaf(kf, 4.37113882867379290e-8f, r);             // - k * lo correction
    float r2 = r * r;
    float ps = fmaf(r2, 2.7557314297e-06f, -1.9841270114e-04f);
    ps = fmaf(r2, ps, 8.3333337680e-03f);
    ps = fmaf(r2, ps, -1.6666667163e-01f);
    float sr = fmaf(r * r2, ps, r);
    float pc = fmaf(r2, -2.7557314297e-07f, 2.4760126951e-05f);
    pc = fmaf(r2, pc, -1.3888889225e-03f);
    pc = fmaf(r2, pc, 4.1666667908e-02f);
    float cr = fmaf(r2 * r2, pc, fmaf(r2, -0.5f, 1.0f));
    switch (k & 3) {
        case 0: *s = sr;  *c = cr;  break;
        case 1: *s = cr;  *c = -sr; break;
        case 2: *s = -sr; *c = -cr; break;
        default:*s = -cr; *c = sr;  break;
    }
}

__global__ __launch_bounds__(NT) void fused_kernel(
    const float* __restrict__ inp,      // (N,L)
    const float* __restrict__ theta,    // (L,M)
    const float* __restrict__ coef,     // (M,)
    const float* __restrict__ rand_u,   // (L,N)
    float* __restrict__ out)            // N*L bits then N probs
{
    extern __shared__ float sm[];
    float2* ab  = reinterpret_cast<float2*>(sm + SM_AB);  // [l*MM+m]
    float*  cp  = sm + SM_CP;
    float*  ush = sm + SM_U;
    float*  prt = sm + SM_PART;

    const int n = blockIdx.x, tid = threadIdx.x;
    const int lane = tid & 31, wid = tid >> 5;

    // ---- Phase A: embedding tile in smem (f32 rounding matches reference) ----
    const float PI2F = 1.57079637050628662109375f;   // fl32(pi/2)
#pragma unroll
    for (int e = tid; e < LL * MM; e += NT) {
        int l = e / MM, m = e % MM;
        float ang = inp[n * LL + l] * ((float)(m + 1) * PI2F);
        float sa, ca; sincos_acc(ang, &sa, &ca);
        float st, ct; sincos_acc(theta[e], &st, &ct);
        float cf = coef[m];
        ab[e] = make_float2(cf * (ct * ca - st * sa),   // a (p=0 comp)
                            cf * (st * ca + ct * sa));  // b (p=1 comp)
    }
    if (tid < LL) ush[tid] = rand_u[tid * NN + n];
    __syncthreads();

    // ---- segment decode: lane owns pairs (m, kst..kst+cnt-1), single m ----
    int m = 0, kst = 0, cnt = 0;
    {
        int seg = tid;
        for (int mm = 0; mm < MM; mm++) {
            int ns = (MM - mm + ZPJ - 1) / ZPJ;
            if (seg < ns) { m = mm; kst = mm + seg * ZPJ;
                            cnt = min(ZPJ, MM - kst); break; }
            seg -= ns;
        }
        // tid >= 120: cnt stays 0 (inactive lane, all weights 0)
    }

    // ---- Phase B: backward scan, store every 4th suffix row (w baked in) ----
    {
        float run[ZPJ];
#pragma unroll
        for (int j = 0; j < ZPJ; j++)
            run[j] = (j < cnt) ? ((kst + j == m) ? 1.0f : 2.0f) : 0.0f;
        for (int l = LL - 1; l >= 0; l--) {
            if ((l & 3) == 3) {                 // run == SUF(l) here
                float* row = cp + (l >> 2) * CPW + tid * ZPJ;
#pragma unroll
                for (int q = 0; q < 3; q++)
                    reinterpret_cast<float4*>(row)[q] =
                        make_float4(run[4*q], run[4*q+1], run[4*q+2], run[4*q+3]);
            }
            float2 vm = ab[l * MM + m];
#pragma unroll
            for (int j = 0; j < ZPJ; j++) {
                float2 vk = ab[l * MM + kst + j];
                run[j] *= fmaf(vm.x, vk.x, vm.y * vk.y);
            }
        }
    }
    __syncthreads();   // harmless ordering point before the zipper

    // ---- Phase C: zipper, 12 blocks of 4 sites ----
    float P[ZPJ];
#pragma unroll
    for (int j = 0; j < ZPJ; j++) P[j] = (j < cnt) ? 1.0f : 0.0f;

    float denom0 = 1.0f;
    int Kexp = 0;
    unsigned long long bits = 0ull;

    float aa[4][ZPJ], bb[4][ZPJ], r[4][ZPJ];

#pragma unroll 1
    for (int b = 0; b < CPROWS; b++) {
        const int l0 = 4 * b;
        // aa/bb for the 4 block sites (registers; smem reads off the chain)
#pragma unroll
        for (int li = 0; li < 4; li++) {
            float2 vm = ab[(l0 + li) * MM + m];
#pragma unroll
            for (int j = 0; j < ZPJ; j++) {
                float2 vk = ab[(l0 + li) * MM + kst + j];
                aa[li][j] = vm.x * vk.x;
                bb[li][j] = vm.y * vk.y;
            }
        }
        // checkpoint row -> r[3]; reconstruct r[2],r[1],r[0]
        {
            const float* crow = cp + b * CPW + tid * ZPJ;
#pragma unroll
            for (int q = 0; q < 3; q++) {
                float4 v = reinterpret_cast<const float4*>(crow)[q];
                r[3][4*q] = v.x; r[3][4*q+1] = v.y; r[3][4*q+2] = v.z; r[3][4*q+3] = v.w;
            }
#pragma unroll
            for (int j = 0; j < ZPJ; j++) {
                r[2][j] = r[3][j] * (aa[3][j] + bb[3][j]);   // SUF(l0+2)
                r[1][j] = r[2][j] * (aa[2][j] + bb[2][j]);   // SUF(l0+1)
                r[0][j] = r[1][j] * (aa[1][j] + bb[1][j]);   // SUF(l0)
            }
        }
        // 4 sequential decision steps
#pragma unroll
        for (int li = 0; li < 4; li++) {
            const int l = l0 + li;
            float s0 = 0.f, s1 = 0.f, t0 = 0.f, t1 = 0.f;
#pragma unroll
            for (int j = 0; j < ZPJ; j++) {
                float ps = P[j] * r[li][j];
                if (j & 1) { t0 = fmaf(ps, aa[li][j], t0); t1 = fmaf(ps, bb[li][j], t1); }
                else       { s0 = fmaf(ps, aa[li][j], s0); s1 = fmaf(ps, bb[li][j], s1); }
            }
            s0 += t0; s1 += t1;
#pragma unroll
            for (int o = 16; o; o >>= 1) {
                s0 += __shfl_xor_sync(0xffffffffu, s0, o);
                s1 += __shfl_xor_sync(0xffffffffu, s1, o);
            }
            if (lane == 0) { prt[(l & 1) * 8 + wid] = s0; prt[(l & 1) * 8 + 4 + wid] = s1; }
            __syncthreads();

            const float* q = prt + (l & 1) * 8;
            float S0 = (q[0] + q[1]) + (q[2] + q[3]);
            float S1 = (q[4] + q[5]) + (q[6] + q[7]);
            float den = fabsf(S0 + S1);
            int bit = (ush[l] * den < fabsf(S1)) ? 1 : 0;   // u < |S1|/den
            if (l == 0) denom0 = den;
            int eb = (__float_as_int(den) >> 23) & 0xFF;    // exact 2^-k renorm
            int kk = eb ? (eb - 127) >> 1 : 0;
            Kexp += kk;
            float scale = __int_as_float((127 - kk) << 23);
            bits |= (unsigned long long)bit << l;
#pragma unroll
            for (int j = 0; j < ZPJ; j++)
                P[j] *= (bit ? bb[li][j] : aa[li][j]) * scale;
        }
    }

    // ---- epilogue: final inner = sum w*P (true value *2^Kexp), outputs ----
    float sf = 0.0f;
#pragma unroll
    for (int j = 0; j < ZPJ; j++) {
        float w = (j < cnt) ? ((kst + j == m) ? 1.0f : 2.0f) : 0.0f;
        sf += w * P[j];
    }
#pragma unroll
    for (int o = 16; o; o >>= 1) sf += __shfl_xor_sync(0xffffffffu, sf, o);
    if (lane == 0) prt[wid] = sf;
    __syncthreads();

    if (tid < LL) out[n * LL + tid] = (float)((bits >> tid) & 1ull);
    if (tid == 0) {
        double Sf = (double)((prt[0] + prt[1]) + (prt[2] + prt[3]));
        double pmv = ldexp(fabs(Sf), Kexp) / (double)denom0;
        out[NN * LL + n] = (float)pmv;
    }
}

extern "C" void kernel_launch(void* const* d_in, const int* in_sizes, int n_in,
                              void* d_out, int out_size) {
    const float* inp    = (const float*)d_in[0];   // (N,L)
    const float* theta  = (const float*)d_in[1];   // (L,M)
    const float* coef   = (const float*)d_in[2];   // (M,)
    const float* rand_u = (const float*)d_in[3];   // (L,N)
    float* out = (float*)d_out;

    static int smem_set = 0;
    if (!smem_set) {
        cudaFuncSetAttribute(fused_kernel,
                             cudaFuncAttributeMaxDynamicSharedMemorySize,
                             SMEMF * (int)sizeof(float));
        smem_set = 1;
    }
    fused_kernel<<<NN, NT, SMEMF * sizeof(float)>>>(inp, theta, coef, rand_u, out);
}